// round 10
// baseline (speedup 1.0000x reference)
#include <cuda_runtime.h>

// Problem constants
#define MAXN 100000
#define MAXE 1600000
#define FIN 64
#define HID 64
#define NCLS 32
#define SCAN_B 512
#define MAXBLK 256   // max scan blocks (MAXN/SCAN_B = 196)

typedef unsigned long long ull;

// ---------------- scratch (static device globals; no allocation) -------------
__device__ int   g_is64;
__device__ int   g_deg[MAXN];
__device__ int   g_rowtmp[MAXN];
__device__ int   g_bsum[MAXBLK];
__device__ int   g_boff[MAXBLK];
__device__ int   g_rowptr[MAXN + 1];
__device__ int   g_cursor[MAXN];
__device__ float g_dinv[MAXN];
__device__ int2  g_csr[MAXE];          // {col, float_as_int(weight)}
__device__ float g_bufA[MAXN * 64];
__device__ float g_bufB[MAXN * 64];
__device__ float g_bufC[MAXN * 64];

__device__ __forceinline__ float* selbuf(int s) {
    return (s == 0) ? g_bufA : (s == 1) ? g_bufB : g_bufC;
}

__device__ __forceinline__ int edge_at(const void* ei, int e) {
    if (g_is64) return (int)((const long long*)ei)[e];
    return ((const int*)ei)[e];
}

// ---------------- packed f32x2 helpers (sm_103a) ------------------------------
__device__ __forceinline__ ull pack2(float lo, float hi) {
    ull r; asm("mov.b64 %0, {%1, %2};" : "=l"(r) : "f"(lo), "f"(hi)); return r;
}
__device__ __forceinline__ void unpack2(ull v, float& lo, float& hi) {
    asm("mov.b64 {%0, %1}, %2;" : "=f"(lo), "=f"(hi) : "l"(v));
}
__device__ __forceinline__ ull ffma2(ull a, ull b, ull c) {
    ull d; asm("fma.rn.f32x2 %0, %1, %2, %3;" : "=l"(d) : "l"(a), "l"(b), "l"(c));
    return d;
}

// ---------------- threefry2x32 (20 rounds) -----------------------------------
__device__ __forceinline__ unsigned rotl32(unsigned x, int d) {
    return (x << d) | (x >> (32 - d));
}

__device__ __forceinline__ void tf20(unsigned k0, unsigned k1,
                                     unsigned c0, unsigned c1,
                                     unsigned& o0, unsigned& o1) {
    unsigned ks0 = k0, ks1 = k1, ks2 = 0x1BD11BDAu ^ k0 ^ k1;
    unsigned x0 = c0 + ks0, x1 = c1 + ks1;
#define TFR(r) { x0 += x1; x1 = rotl32(x1, (r)); x1 ^= x0; }
    TFR(13) TFR(15) TFR(26) TFR(6)
    x0 += ks1; x1 += ks2 + 1u;
    TFR(17) TFR(29) TFR(16) TFR(24)
    x0 += ks2; x1 += ks0 + 2u;
    TFR(13) TFR(15) TFR(26) TFR(6)
    x0 += ks0; x1 += ks1 + 3u;
    TFR(17) TFR(29) TFR(16) TFR(24)
    x0 += ks1; x1 += ks2 + 4u;
    TFR(13) TFR(15) TFR(26) TFR(6)
    x0 += ks2; x1 += ks0 + 5u;
#undef TFR
    o0 = x0; o1 = x1;
}

__device__ __forceinline__ bool keep_elem(int i) {
    unsigned o0, o1;
    tf20(0u, 42u, 0u, (unsigned)i, o0, o1);
    unsigned bits = o0 ^ o1;
    float u = __uint_as_float((bits >> 9) | 0x3F800000u) - 1.0f;
    return u < 0.5f;
}

// ---------------- setup kernels ----------------------------------------------
__global__ void zero_detect_kernel(const unsigned* __restrict__ w, int n) {
    int i = blockIdx.x * blockDim.x + threadIdx.x;
    if (i < n) g_deg[i] = 0;
    if (i == 0) {
        int is64 = 1;
        #pragma unroll
        for (int k = 0; k < 8; k++)
            if (w[2 * k + 1] != 0u) is64 = 0;
        g_is64 = is64;
    }
}

__global__ void deg_hist_kernel(const void* __restrict__ ei, int E) {
    int e = blockIdx.x * blockDim.x + threadIdx.x;
    if (e < E) {
        int r = edge_at(ei, e);
        atomicAdd(&g_deg[r], 1);
    }
}

__global__ void scan_local_kernel(int n) {
    __shared__ int sh[SCAN_B];
    int t = threadIdx.x;
    int i = blockIdx.x * SCAN_B + t;
    int v = (i < n) ? g_deg[i] : 0;
    sh[t] = v;
    __syncthreads();
    for (int off = 1; off < SCAN_B; off <<= 1) {
        int u = (t >= off) ? sh[t - off] : 0;
        __syncthreads();
        if (t >= off) sh[t] += u;
        __syncthreads();
    }
    if (i < n) g_rowtmp[i] = sh[t] - v;
    if (t == SCAN_B - 1) g_bsum[blockIdx.x] = sh[t];
}

__global__ void scan_bsums_kernel(int nb) {
    __shared__ int sh[MAXBLK];
    int t = threadIdx.x;
    int v = (t < nb) ? g_bsum[t] : 0;
    sh[t] = v;
    __syncthreads();
    for (int off = 1; off < MAXBLK; off <<= 1) {
        int u = (t >= off) ? sh[t - off] : 0;
        __syncthreads();
        if (t >= off) sh[t] += u;
        __syncthreads();
    }
    if (t < nb) g_boff[t] = sh[t] - v;
}

__global__ void scan_final_kernel(int n, int E) {
    int i = blockIdx.x * blockDim.x + threadIdx.x;
    if (i < n) {
        int v = g_rowtmp[i] + g_boff[i / SCAN_B];
        g_rowptr[i] = v;
        g_cursor[i] = v;
        int d = g_deg[i];
        g_dinv[i] = (d > 0) ? rsqrtf((float)d) : 0.0f;
    }
    if (i == 0) g_rowptr[n] = E;
}

__global__ void scatter_kernel(const void* __restrict__ ei, int E) {
    int e = blockIdx.x * blockDim.x + threadIdx.x;
    if (e < E) {
        int r = edge_at(ei, e);
        int c = edge_at(ei, E + e);
        int pos = atomicAdd(&g_cursor[r], 1);
        float w = -(g_dinv[r] * g_dinv[c]);
        g_csr[pos] = make_int2(c, __float_as_int(w));
    }
}

// ---------------- SpMM v3: f32x2 accum, 8-deep gather unroll -----------------
__global__ void spmm_kernel(const float* __restrict__ ext_src, int src_sel,
                            int dst_sel,
                            const float* __restrict__ ext_other, int other_sel,
                            int mode, int n) {
    const float* src = (src_sel < 0) ? ext_src : selbuf(src_sel);
    float*       dst = selbuf(dst_sel);
    int node = (blockIdx.x * blockDim.x + threadIdx.x) >> 5;
    int lane = threadIdx.x & 31;
    if (node >= n) return;
    int start = g_rowptr[node];
    int end   = g_rowptr[node + 1];
    const ull* s8 = (const ull*)src;   // float2 as 64-bit
    ull acc = 0ull;                    // packed (0.0f, 0.0f)

    for (int base = start; base < end; base += 32) {
        int idx = base + lane;
        int2 ce = make_int2(0, 0);
        if (idx < end) ce = g_csr[idx];
        int cnt = min(32, end - base);
        int j = 0;
        for (; j + 8 <= cnt; j += 8) {
            int c0 = __shfl_sync(0xffffffffu, ce.x, j);
            int c1 = __shfl_sync(0xffffffffu, ce.x, j + 1);
            int c2 = __shfl_sync(0xffffffffu, ce.x, j + 2);
            int c3 = __shfl_sync(0xffffffffu, ce.x, j + 3);
            int c4 = __shfl_sync(0xffffffffu, ce.x, j + 4);
            int c5 = __shfl_sync(0xffffffffu, ce.x, j + 5);
            int c6 = __shfl_sync(0xffffffffu, ce.x, j + 6);
            int c7 = __shfl_sync(0xffffffffu, ce.x, j + 7);
            float w0 = __int_as_float(__shfl_sync(0xffffffffu, ce.y, j));
            float w1 = __int_as_float(__shfl_sync(0xffffffffu, ce.y, j + 1));
            float w2 = __int_as_float(__shfl_sync(0xffffffffu, ce.y, j + 2));
            float w3 = __int_as_float(__shfl_sync(0xffffffffu, ce.y, j + 3));
            float w4 = __int_as_float(__shfl_sync(0xffffffffu, ce.y, j + 4));
            float w5 = __int_as_float(__shfl_sync(0xffffffffu, ce.y, j + 5));
            float w6 = __int_as_float(__shfl_sync(0xffffffffu, ce.y, j + 6));
            float w7 = __int_as_float(__shfl_sync(0xffffffffu, ce.y, j + 7));
            ull v0 = __ldg(&s8[c0 * 32 + lane]);
            ull v1 = __ldg(&s8[c1 * 32 + lane]);
            ull v2 = __ldg(&s8[c2 * 32 + lane]);
            ull v3 = __ldg(&s8[c3 * 32 + lane]);
            ull v4 = __ldg(&s8[c4 * 32 + lane]);
            ull v5 = __ldg(&s8[c5 * 32 + lane]);
            ull v6 = __ldg(&s8[c6 * 32 + lane]);
            ull v7 = __ldg(&s8[c7 * 32 + lane]);
            acc = ffma2(pack2(w0, w0), v0, acc);
            acc = ffma2(pack2(w1, w1), v1, acc);
            acc = ffma2(pack2(w2, w2), v2, acc);
            acc = ffma2(pack2(w3, w3), v3, acc);
            acc = ffma2(pack2(w4, w4), v4, acc);
            acc = ffma2(pack2(w5, w5), v5, acc);
            acc = ffma2(pack2(w6, w6), v6, acc);
            acc = ffma2(pack2(w7, w7), v7, acc);
        }
        for (; j < cnt; j++) {
            int   c = __shfl_sync(0xffffffffu, ce.x, j);
            float w = __int_as_float(__shfl_sync(0xffffffffu, ce.y, j));
            ull v = __ldg(&s8[c * 32 + lane]);
            acc = ffma2(pack2(w, w), v, acc);
        }
    }
    float ax, ay;
    unpack2(acc, ax, ay);
    if (mode) {
        const float* oth = (other_sel < 0) ? ext_other : selbuf(other_sel);
        float2 o = ((const float2*)oth)[node * 32 + lane];
        ax = 2.0f * ax - o.x;
        ay = 2.0f * ay - o.y;
    }
    ((float2*)dst)[node * 32 + lane] = make_float2(ax, ay);
}

// ---------------- GEMM1: h = dropout(relu(x@W0 + A@W1 + B@W2 + b)) -----------
// 256 threads; 2 nodes/thread; packed f32x2 accumulators (8 per node)
__global__ void __launch_bounds__(256) gemm1_kernel(
        const float* __restrict__ x,
        const float* __restrict__ W,
        const float* __restrict__ b, int n) {
    __shared__ float sw[3 * 64 * 64];  // 48KB
    for (int i = threadIdx.x; i < 3 * 64 * 64 / 4; i += 256)
        ((float4*)sw)[i] = ((const float4*)W)[i];
    __syncthreads();

    int local = threadIdx.x >> 2;              // 0..63
    int jb    = (threadIdx.x & 3) * 16;
    int node0 = blockIdx.x * 128 + local;
    int node1 = node0 + 64;
    if (node0 >= n) return;
    bool v1 = (node1 < n);
    int nd1 = v1 ? node1 : node0;

    ull acc0[8], acc1[8];
#pragma unroll
    for (int j = 0; j < 8; j++) {
        ull bp = __ldg((const ull*)&b[jb + 2 * j]);
        acc0[j] = bp; acc1[j] = bp;
    }

    const float* in0[3] = { x + node0 * 64, g_bufA + node0 * 64, g_bufB + node0 * 64 };
    const float* in1[3] = { x + nd1 * 64,   g_bufA + nd1 * 64,   g_bufB + nd1 * 64 };
#pragma unroll
    for (int m = 0; m < 3; m++) {
        const float4* ip0 = (const float4*)in0[m];
        const float4* ip1 = (const float4*)in1[m];
        const float* wm = sw + m * 4096 + jb;
#pragma unroll
        for (int k4 = 0; k4 < 16; k4++) {
            float4 a4 = __ldg(&ip0[k4]);
            float4 b4 = __ldg(&ip1[k4]);
            const float* wr = wm + (k4 * 4) * 64;
#pragma unroll
            for (int c = 0; c < 4; c++) {
                float av = ((const float*)&a4)[c];
                float bv = ((const float*)&b4)[c];
                ull av2 = pack2(av, av);
                ull bv2 = pack2(bv, bv);
                const ull* wrow = (const ull*)(wr + c * 64);
#pragma unroll
                for (int j = 0; j < 8; j++) {
                    ull w2 = wrow[j];
                    acc0[j] = ffma2(av2, w2, acc0[j]);
                    acc1[j] = ffma2(bv2, w2, acc1[j]);
                }
            }
        }
    }
    // relu + dropout fused epilogue
    {
        float t[16];
#pragma unroll
        for (int j = 0; j < 8; j++) unpack2(acc0[j], t[2 * j], t[2 * j + 1]);
        float* op = g_bufC + node0 * 64 + jb;
        int ib = node0 * 64 + jb;
#pragma unroll
        for (int q = 0; q < 4; q++) {
            float4 o;
            o.x = keep_elem(ib + q * 4 + 0) ? 2.0f * fmaxf(t[q * 4 + 0], 0.f) : 0.f;
            o.y = keep_elem(ib + q * 4 + 1) ? 2.0f * fmaxf(t[q * 4 + 1], 0.f) : 0.f;
            o.z = keep_elem(ib + q * 4 + 2) ? 2.0f * fmaxf(t[q * 4 + 2], 0.f) : 0.f;
            o.w = keep_elem(ib + q * 4 + 3) ? 2.0f * fmaxf(t[q * 4 + 3], 0.f) : 0.f;
            ((float4*)op)[q] = o;
        }
    }
    if (v1) {
        float t[16];
#pragma unroll
        for (int j = 0; j < 8; j++) unpack2(acc1[j], t[2 * j], t[2 * j + 1]);
        float* op = g_bufC + node1 * 64 + jb;
        int ib = node1 * 64 + jb;
#pragma unroll
        for (int q = 0; q < 4; q++) {
            float4 o;
            o.x = keep_elem(ib + q * 4 + 0) ? 2.0f * fmaxf(t[q * 4 + 0], 0.f) : 0.f;
            o.y = keep_elem(ib + q * 4 + 1) ? 2.0f * fmaxf(t[q * 4 + 1], 0.f) : 0.f;
            o.z = keep_elem(ib + q * 4 + 2) ? 2.0f * fmaxf(t[q * 4 + 2], 0.f) : 0.f;
            o.w = keep_elem(ib + q * 4 + 3) ? 2.0f * fmaxf(t[q * 4 + 3], 0.f) : 0.f;
            ((float4*)op)[q] = o;
        }
    }
}

// ---------------- GEMM2: out = log_softmax(h@W0 + A@W1 + B@W2 + b) -----------
// 256 threads; 2 nodes/thread; packed f32x2 accumulators
__global__ void __launch_bounds__(256) gemm2_kernel(
        const float* __restrict__ W,
        const float* __restrict__ b,
        float* __restrict__ out, int n) {
    __shared__ float sw[3 * 64 * 32];  // 24KB
    for (int i = threadIdx.x; i < 3 * 64 * 32 / 4; i += 256)
        ((float4*)sw)[i] = ((const float4*)W)[i];
    __syncthreads();

    int local = threadIdx.x >> 1;              // 0..127
    int jb    = (threadIdx.x & 1) * 16;
    int node0 = blockIdx.x * 256 + local;
    int node1 = node0 + 128;
    bool v0 = (node0 < n);
    bool v1 = (node1 < n);
    int nd0 = v0 ? node0 : 0;
    int nd1 = v1 ? node1 : nd0;

    ull acc0[8], acc1[8];
#pragma unroll
    for (int j = 0; j < 8; j++) {
        ull bp = __ldg((const ull*)&b[jb + 2 * j]);
        acc0[j] = bp; acc1[j] = bp;
    }

    const float* in0[3] = { g_bufC + nd0 * 64, g_bufA + nd0 * 64, g_bufB + nd0 * 64 };
    const float* in1[3] = { g_bufC + nd1 * 64, g_bufA + nd1 * 64, g_bufB + nd1 * 64 };
#pragma unroll
    for (int m = 0; m < 3; m++) {
        const float4* ip0 = (const float4*)in0[m];
        const float4* ip1 = (const float4*)in1[m];
        const float* wm = sw + m * 2048 + jb;
#pragma unroll
        for (int k4 = 0; k4 < 16; k4++) {
            float4 a4 = __ldg(&ip0[k4]);
            float4 b4 = __ldg(&ip1[k4]);
            const float* wr = wm + (k4 * 4) * 32;
#pragma unroll
            for (int c = 0; c < 4; c++) {
                float av = ((const float*)&a4)[c];
                float bv = ((const float*)&b4)[c];
                ull av2 = pack2(av, av);
                ull bv2 = pack2(bv, bv);
                const ull* wrow = (const ull*)(wr + c * 32);
#pragma unroll
                for (int j = 0; j < 8; j++) {
                    ull w2 = wrow[j];
                    acc0[j] = ffma2(av2, w2, acc0[j]);
                    acc1[j] = ffma2(bv2, w2, acc1[j]);
                }
            }
        }
    }
    float t0[16], t1[16];
#pragma unroll
    for (int j = 0; j < 8; j++) {
        unpack2(acc0[j], t0[2 * j], t0[2 * j + 1]);
        unpack2(acc1[j], t1[2 * j], t1[2 * j + 1]);
    }
    // log_softmax per node; threads (t, t^1) share the two class halves
    float mx0 = t0[0], mx1 = t1[0];
#pragma unroll
    for (int jj = 1; jj < 16; jj++) { mx0 = fmaxf(mx0, t0[jj]); mx1 = fmaxf(mx1, t1[jj]); }
    float M0 = fmaxf(mx0, __shfl_xor_sync(0xffffffffu, mx0, 1));
    float M1 = fmaxf(mx1, __shfl_xor_sync(0xffffffffu, mx1, 1));
    float s0 = 0.f, s1 = 0.f;
#pragma unroll
    for (int jj = 0; jj < 16; jj++) { s0 += expf(t0[jj] - M0); s1 += expf(t1[jj] - M1); }
    s0 += __shfl_xor_sync(0xffffffffu, s0, 1);
    s1 += __shfl_xor_sync(0xffffffffu, s1, 1);
    float lse0 = M0 + logf(s0);
    float lse1 = M1 + logf(s1);
    if (v0) {
        float* op = out + node0 * 32 + jb;
#pragma unroll
        for (int q = 0; q < 4; q++) {
            float4 o;
            o.x = t0[q * 4 + 0] - lse0; o.y = t0[q * 4 + 1] - lse0;
            o.z = t0[q * 4 + 2] - lse0; o.w = t0[q * 4 + 3] - lse0;
            ((float4*)op)[q] = o;
        }
    }
    if (v1) {
        float* op = out + node1 * 32 + jb;
#pragma unroll
        for (int q = 0; q < 4; q++) {
            float4 o;
            o.x = t1[q * 4 + 0] - lse1; o.y = t1[q * 4 + 1] - lse1;
            o.z = t1[q * 4 + 2] - lse1; o.w = t1[q * 4 + 3] - lse1;
            ((float4*)op)[q] = o;
        }
    }
}

// ---------------- launch ------------------------------------------------------
extern "C" void kernel_launch(void* const* d_in, const int* in_sizes, int n_in,
                              void* d_out, int out_size) {
    const float* x  = (const float*)d_in[0];
    const void*  ei = d_in[1];
    const float* W1 = (const float*)d_in[2];
    const float* b1 = (const float*)d_in[3];
    const float* W2 = (const float*)d_in[4];
    const float* b2 = (const float*)d_in[5];
    float* out = (float*)d_out;

    int n = in_sizes[0] / FIN;       // 100000
    int E = in_sizes[1] / 2;         // 1600000

    const int T = 256;
    int gN  = (n + T - 1) / T;
    int gE  = (E + T - 1) / T;
    int gW  = (n * 32 + T - 1) / T;
    int gG1 = (n + 127) / 128;
    int gG2 = (n + 255) / 256;
    int nb  = (n + SCAN_B - 1) / SCAN_B;

    zero_detect_kernel<<<gN, T>>>((const unsigned*)ei, n);
    deg_hist_kernel<<<gE, T>>>(ei, E);
    scan_local_kernel<<<nb, SCAN_B>>>(n);
    scan_bsums_kernel<<<1, MAXBLK>>>(nb);
    scan_final_kernel<<<gN, T>>>(n, E);
    scatter_kernel<<<gE, T>>>(ei, E);

    spmm_kernel<<<gW, T>>>(x, -1, 0, nullptr, -2, 0, n);
    spmm_kernel<<<gW, T>>>(nullptr, 0, 1, x, -1, 1, n);
    gemm1_kernel<<<gG1, T>>>(x, W1, b1, n);

    spmm_kernel<<<gW, T>>>(nullptr, 2, 0, nullptr, -2, 0, n);
    spmm_kernel<<<gW, T>>>(nullptr, 0, 1, nullptr, 2, 1, n);
    gemm2_kernel<<<gG2, T>>>(W2, b2, out, n);
}